// round 10
// baseline (speedup 1.0000x reference)
#include <cuda_runtime.h>
#include <cuda_bf16.h>
#include <cuda_fp16.h>
#include <math.h>
#include <stdint.h>

// ---------------------------------------------------------------------------
// MultilayerGRU: B=32, S=512, I=H=O=1024, L=2
// R10: recurrence grid halved (NBLK=64, 32 z|r cols + 16 g cols per block).
//      Barrier atomic serialization and L2 broadcast traffic both scale with
//      block count -> ~3 us/step saved. Numerics identical to R9 (fp16
//      phase-1, fp16 hi/lo phase-2, fp32 master h). Big GEMMs = bf16 k_hmma.
// ---------------------------------------------------------------------------

#define B_  32
#define S_  512
#define IN_ 1024
#define H_  1024
#define OUT_ 1024
#define L_  2
#define M_  (B_ * S_)      /* 16384 */
#define N3_ (3 * H_)       /* 3072  */
#define NBLK 64

// ---------------- device scratch ------------------------------------------
__device__ float g_gx[(size_t)M_ * N3_];   // x-projections for current layer
__device__ float g_h[B_ * H_];             // fp32 master hidden state
__device__ float g_z[B_ * H_];             // z gate

__device__ __align__(16) unsigned short g_hf[B_ * H_];                  // h fp16
__device__ __align__(16) unsigned short g_rhh[B_ * H_], g_rhl[B_ * H_]; // r*h fp16 hi/lo

// bf16 hi/lo operand buffers (GEMM path)
__device__ __align__(16) unsigned short g_xh[(size_t)M_ * IN_],  g_xl[(size_t)M_ * IN_];
__device__ __align__(16) unsigned short g_seqh[(size_t)M_ * H_], g_seql[(size_t)M_ * H_];
__device__ __align__(16) unsigned short g_wzxh[(size_t)L_ * H_ * IN_], g_wzxl[(size_t)L_ * H_ * IN_];
__device__ __align__(16) unsigned short g_wrxh[(size_t)L_ * H_ * IN_], g_wrxl[(size_t)L_ * H_ * IN_];
__device__ __align__(16) unsigned short g_wgxh[(size_t)L_ * H_ * IN_], g_wgxl[(size_t)L_ * H_ * IN_];
__device__ __align__(16) unsigned short g_woh[(size_t)OUT_ * H_],      g_wol[(size_t)OUT_ * H_];

// fp16 recurrence weights
__device__ __align__(16) unsigned short g_wzhf[(size_t)L_ * H_ * H_];
__device__ __align__(16) unsigned short g_wrhf[(size_t)L_ * H_ * H_];
__device__ __align__(16) unsigned short g_wghh16[(size_t)L_ * H_ * H_];
__device__ __align__(16) unsigned short g_wghl16[(size_t)L_ * H_ * H_];

// grid barrier (generation-based; replay-safe)
__device__ unsigned g_bar_count = 0;
__device__ volatile unsigned g_bar_gen = 0;

__device__ __forceinline__ void grid_sync() {
    __syncthreads();
    if (threadIdx.x == 0) {
        __threadfence();
        unsigned gen = g_bar_gen;
        if (atomicAdd(&g_bar_count, 1u) == NBLK - 1u) {
            g_bar_count = 0;
            __threadfence();
            g_bar_gen = gen + 1u;
        } else {
            while (g_bar_gen == gen) { }
        }
    }
    __syncthreads();
}

// ---------------------------------------------------------------------------
__device__ __forceinline__ void split1(float v, unsigned short& h, unsigned short& l) {
    __nv_bfloat16 hb = __float2bfloat16(v);
    float r = v - __bfloat162float(hb);
    __nv_bfloat16 lb = __float2bfloat16(r);
    h = __bfloat16_as_ushort(hb);
    l = __bfloat16_as_ushort(lb);
}

__device__ __forceinline__ void split16(float v, unsigned short& h, unsigned short& l) {
    __half hh = __float2half(v);
    float r = v - __half2float(hh);
    h = __half_as_ushort(hh);
    l = __half_as_ushort(__float2half(r));
}

// mma.sync m16n8k16 row.col, bf16 and fp16 flavors
__device__ __forceinline__ void mma_bf16(float* c, const uint32_t* a, const uint32_t* b) {
    asm volatile(
        "mma.sync.aligned.m16n8k16.row.col.f32.bf16.bf16.f32 "
        "{%0,%1,%2,%3}, {%4,%5,%6,%7}, {%8,%9}, {%0,%1,%2,%3};"
        : "+f"(c[0]), "+f"(c[1]), "+f"(c[2]), "+f"(c[3])
        : "r"(a[0]), "r"(a[1]), "r"(a[2]), "r"(a[3]), "r"(b[0]), "r"(b[1]));
}

__device__ __forceinline__ void mma_f16(float* c, const uint32_t* a, const uint32_t* b) {
    asm volatile(
        "mma.sync.aligned.m16n8k16.row.col.f32.f16.f16.f32 "
        "{%0,%1,%2,%3}, {%4,%5,%6,%7}, {%8,%9}, {%0,%1,%2,%3};"
        : "+f"(c[0]), "+f"(c[1]), "+f"(c[2]), "+f"(c[3])
        : "r"(a[0]), "r"(a[1]), "r"(a[2]), "r"(a[3]), "r"(b[0]), "r"(b[1]));
}

__device__ __forceinline__ float sigmoidf_(float x) {
    return 1.f / (1.f + expf(-x));
}

// ---------------------------------------------------------------------------
// x[b][t][i] -> hi/lo bf16 [t*B+b][i]
// ---------------------------------------------------------------------------
__global__ void k_transpose_x(const float* __restrict__ x) {
    int row = blockIdx.x;
    int t = row / B_;
    int b = row % B_;
    const float4* src = (const float4*)(x + ((size_t)b * S_ + t) * IN_);
    ushort4* dh = (ushort4*)(g_xh + (size_t)row * IN_);
    ushort4* dl = (ushort4*)(g_xl + (size_t)row * IN_);
    for (int i = threadIdx.x; i < IN_ / 4; i += blockDim.x) {
        float4 v = src[i];
        ushort4 h, l;
        split1(v.x, h.x, l.x);
        split1(v.y, h.y, l.y);
        split1(v.z, h.z, l.z);
        split1(v.w, h.w, l.w);
        dh[i] = h;
        dl[i] = l;
    }
}

// ---------------------------------------------------------------------------
// weight splits
// ---------------------------------------------------------------------------
__global__ void k_split(const float* __restrict__ src, int wsel, int n4) {
    int i = blockIdx.x * blockDim.x + threadIdx.x;
    if (i >= n4) return;
    unsigned short* hi;
    unsigned short* lo;
    switch (wsel) {
        case 0: hi = g_wzxh; lo = g_wzxl; break;
        case 1: hi = g_wrxh; lo = g_wrxl; break;
        case 2: hi = g_wgxh; lo = g_wgxl; break;
        default: hi = g_woh;  lo = g_wol; break;
    }
    float4 v = ((const float4*)src)[i];
    ushort4 h, l;
    split1(v.x, h.x, l.x);
    split1(v.y, h.y, l.y);
    split1(v.z, h.z, l.z);
    split1(v.w, h.w, l.w);
    ((ushort4*)hi)[i] = h;
    ((ushort4*)lo)[i] = l;
}

__global__ void k_split16(const float* __restrict__ src, int wsel, int n4) {
    int i = blockIdx.x * blockDim.x + threadIdx.x;
    if (i >= n4) return;
    float4 v = ((const float4*)src)[i];
    if (wsel < 2) {
        unsigned short* hi = wsel ? g_wrhf : g_wzhf;
        ushort4 h;
        h.x = __half_as_ushort(__float2half(v.x));
        h.y = __half_as_ushort(__float2half(v.y));
        h.z = __half_as_ushort(__float2half(v.z));
        h.w = __half_as_ushort(__float2half(v.w));
        ((ushort4*)hi)[i] = h;
    } else {
        ushort4 h, l;
        split16(v.x, h.x, l.x);
        split16(v.y, h.y, l.y);
        split16(v.z, h.z, l.z);
        split16(v.w, h.w, l.w);
        ((ushort4*)g_wghh16)[i] = h;
        ((ushort4*)g_wghl16)[i] = l;
    }
}

// ---------------------------------------------------------------------------
// k_prep: g_h / g_hf from h0[b][layer][:]; reset barrier.
// ---------------------------------------------------------------------------
__global__ void k_prep(const float* __restrict__ h0, int layer) {
    int idx = blockIdx.x * blockDim.x + threadIdx.x;  // [0, B*H)
    if (idx == 0) { g_bar_count = 0; g_bar_gen = 0; }
    int b = idx / H_;
    int c = idx % H_;
    float v = h0[((size_t)b * L_ + layer) * H_ + c];
    g_h[idx] = v;
    g_hf[idx] = __half_as_ushort(__float2half(v));
}

// ---------------------------------------------------------------------------
// HMMA split-bf16 GEMM (unchanged, proven).
// ---------------------------------------------------------------------------
#define HMP 40

__global__ void __launch_bounds__(256) k_hmma(
    int asel, int wsel, int woff,
    const float* __restrict__ bias, float* __restrict__ Cout,
    int ldc, int col0, int permC)
{
    __shared__ __align__(16) unsigned short As_h[128 * HMP];
    __shared__ __align__(16) unsigned short As_l[128 * HMP];
    __shared__ __align__(16) unsigned short Bs_h[64 * HMP];
    __shared__ __align__(16) unsigned short Bs_l[64 * HMP];

    const int tid = threadIdx.x;
    const int m0 = blockIdx.y * 128, n0 = blockIdx.x * 64;

    const unsigned short* Ah = asel ? g_seqh : g_xh;
    const unsigned short* Al = asel ? g_seql : g_xl;
    const unsigned short* Wh;
    const unsigned short* Wl;
    switch (wsel) {
        case 0: Wh = g_wzxh; Wl = g_wzxl; break;
        case 1: Wh = g_wrxh; Wl = g_wrxl; break;
        case 2: Wh = g_wgxh; Wl = g_wgxl; break;
        default: Wh = g_woh; Wl = g_wol; break;
    }
    Wh += woff; Wl += woff;

    const int ar0 = (2 * tid) >> 2,     au0 = (2 * tid) & 3;
    const int ar1 = (2 * tid + 1) >> 2, au1 = (2 * tid + 1) & 3;
    const int br  = tid >> 2,           bu  = tid & 3;

    const int warp = tid >> 5, lane = tid & 31;
    const int g = lane >> 2, tg = lane & 3;
    const int wm = warp >> 1, wn = warp & 1;

    float acc[2][4][4];
#pragma unroll
    for (int mt = 0; mt < 2; mt++)
#pragma unroll
        for (int nt = 0; nt < 4; nt++)
#pragma unroll
            for (int i = 0; i < 4; i++) acc[mt][nt][i] = 0.f;

    const uint32_t* Awh = (const uint32_t*)As_h;
    const uint32_t* Awl = (const uint32_t*)As_l;
    const uint32_t* Bwh = (const uint32_t*)Bs_h;
    const uint32_t* Bwl = (const uint32_t*)Bs_l;

    uint4 vah0, vah1, val0, val1, vbh, vbl;
    vah0 = *(const uint4*)(Ah + (size_t)(m0 + ar0) * 1024 + au0 * 8);
    vah1 = *(const uint4*)(Ah + (size_t)(m0 + ar1) * 1024 + au1 * 8);
    val0 = *(const uint4*)(Al + (size_t)(m0 + ar0) * 1024 + au0 * 8);
    val1 = *(const uint4*)(Al + (size_t)(m0 + ar1) * 1024 + au1 * 8);
    vbh  = *(const uint4*)(Wh + (size_t)(n0 + br) * 1024 + bu * 8);
    vbl  = *(const uint4*)(Wl + (size_t)(n0 + br) * 1024 + bu * 8);

    for (int kc = 0; kc < 32; kc++) {
        __syncthreads();
        *(uint4*)(As_h + ar0 * HMP + au0 * 8) = vah0;
        *(uint4*)(As_h + ar1 * HMP + au1 * 8) = vah1;
        *(uint4*)(As_l + ar0 * HMP + au0 * 8) = val0;
        *(uint4*)(As_l + ar1 * HMP + au1 * 8) = val1;
        *(uint4*)(Bs_h + br * HMP + bu * 8) = vbh;
        *(uint4*)(Bs_l + br * HMP + bu * 8) = vbl;
        if (kc + 1 < 32) {
            int ko = (kc + 1) * 32;
            vah0 = *(const uint4*)(Ah + (size_t)(m0 + ar0) * 1024 + ko + au0 * 8);
            vah1 = *(const uint4*)(Ah + (size_t)(m0 + ar1) * 1024 + ko + au1 * 8);
            val0 = *(const uint4*)(Al + (size_t)(m0 + ar0) * 1024 + ko + au0 * 8);
            val1 = *(const uint4*)(Al + (size_t)(m0 + ar1) * 1024 + ko + au1 * 8);
            vbh  = *(const uint4*)(Wh + (size_t)(n0 + br) * 1024 + ko + bu * 8);
            vbl  = *(const uint4*)(Wl + (size_t)(n0 + br) * 1024 + ko + bu * 8);
        }
        __syncthreads();

#pragma unroll
        for (int ks = 0; ks < 2; ks++) {
            const int kw = ks * 8 + tg;
            uint32_t ahf[2][4], alf[2][4];
#pragma unroll
            for (int mt = 0; mt < 2; mt++) {
                int rb = (wm * 32 + mt * 16 + g) * 20 + kw;
                ahf[mt][0] = Awh[rb];
                ahf[mt][1] = Awh[rb + 160];
                ahf[mt][2] = Awh[rb + 4];
                ahf[mt][3] = Awh[rb + 164];
                alf[mt][0] = Awl[rb];
                alf[mt][1] = Awl[rb + 160];
                alf[mt][2] = Awl[rb + 4];
                alf[mt][3] = Awl[rb + 164];
            }
            uint32_t bhf[4][2], blf[4][2];
#pragma unroll
            for (int nt = 0; nt < 4; nt++) {
                int rb = (wn * 32 + nt * 8 + g) * 20 + kw;
                bhf[nt][0] = Bwh[rb];
                bhf[nt][1] = Bwh[rb + 4];
                blf[nt][0] = Bwl[rb];
                blf[nt][1] = Bwl[rb + 4];
            }
#pragma unroll
            for (int mt = 0; mt < 2; mt++)
#pragma unroll
                for (int nt = 0; nt < 4; nt++) {
                    mma_bf16(acc[mt][nt], ahf[mt], bhf[nt]);
                    mma_bf16(acc[mt][nt], ahf[mt], blf[nt]);
                    mma_bf16(acc[mt][nt], alf[mt], bhf[nt]);
                }
        }
    }

#pragma unroll
    for (int mt = 0; mt < 2; mt++) {
#pragma unroll
        for (int nt = 0; nt < 4; nt++) {
            int mrow = m0 + wm * 32 + mt * 16 + g;
            int ncol = n0 + wn * 32 + nt * 8 + tg * 2;
            float bx = bias[ncol], by = bias[ncol + 1];
#pragma unroll
            for (int half = 0; half < 2; half++) {
                int m = mrow + half * 8;
                float2 o;
                o.x = acc[mt][nt][half * 2 + 0] + bx;
                o.y = acc[mt][nt][half * 2 + 1] + by;
                float* dst;
                if (permC) {
                    int b = m & (B_ - 1);
                    int t = m >> 5;
                    dst = Cout + ((size_t)b * S_ + t) * ldc + ncol;
                } else {
                    dst = g_gx + (size_t)m * ldc + col0 + ncol;
                }
                *(float2*)dst = o;
            }
        }
    }
}

// ---------------------------------------------------------------------------
// fp16 tensor-core recurrence, NBLK=64.
//   Phase 1: 32 (z|r) cols/block (blocks 0-31: z, 32-63: r), fp16 1-term.
//   Phase 2: 16 g cols/block, fp16 hi/lo 3-term.
// ---------------------------------------------------------------------------
#define SW_PW 516
#define TILE_B (32 * SW_PW * 4)            /* 66048 bytes per tile buffer */
#define RED_STRIDE 34
#define RED_B (8 * 32 * RED_STRIDE * 4)    /* 34816 */
#define SMEMR (2 * TILE_B + RED_B)         /* 166912 */

__device__ __forceinline__ void stage_one(
    const unsigned short* __restrict__ gsrc, uint32_t* __restrict__ s)
{
    const int tid = threadIdx.x;
#pragma unroll
    for (int rr = 0; rr < 2; rr++) {
        uint4 v[8];
#pragma unroll
        for (int it = 0; it < 8; it++) {
            int idx = tid + 256 * (rr * 8 + it);
            int row = idx >> 7;
            int u = idx & 127;
            v[it] = __ldcg((const uint4*)(gsrc + (size_t)row * H_) + u);
        }
#pragma unroll
        for (int it = 0; it < 8; it++) {
            int idx = tid + 256 * (rr * 8 + it);
            int row = idx >> 7;
            int u = idx & 127;
            *(uint4*)(s + row * SW_PW + u * 4) = v[it];
        }
    }
}

__device__ __forceinline__ void stage_two(
    const unsigned short* __restrict__ gh, const unsigned short* __restrict__ gl,
    uint32_t* __restrict__ sh, uint32_t* __restrict__ sl)
{
    const int tid = threadIdx.x;
#pragma unroll
    for (int rr = 0; rr < 4; rr++) {
        uint4 v[4], w[4];
#pragma unroll
        for (int it = 0; it < 4; it++) {
            int idx = tid + 256 * (rr * 4 + it);
            int row = idx >> 7;
            int u = idx & 127;
            v[it] = __ldcg((const uint4*)(gh + (size_t)row * H_) + u);
            w[it] = __ldcg((const uint4*)(gl + (size_t)row * H_) + u);
        }
#pragma unroll
        for (int it = 0; it < 4; it++) {
            int idx = tid + 256 * (rr * 4 + it);
            int row = idx >> 7;
            int u = idx & 127;
            *(uint4*)(sh + row * SW_PW + u * 4) = v[it];
            *(uint4*)(sl + row * SW_PW + u * 4) = w[it];
        }
    }
}

__global__ void __launch_bounds__(256, 1) k_gru_recur(
    int layer, float* __restrict__ hid_out)
{
    extern __shared__ char smem[];
    uint32_t* s_t0 = (uint32_t*)smem;                    // tile 0
    uint32_t* s_t1 = (uint32_t*)(smem + TILE_B);         // tile 1
    float*    red  = (float*)(smem + 2 * TILE_B);        // [8][32][34]

    const int tid = threadIdx.x;
    const int warp = tid >> 5, lane = tid & 31;
    const int g = lane >> 2, tg = lane & 3;

    // ---- ownership ----
    const int vc   = blockIdx.x * 32;        // [0,2048)
    const int gate = vc >> 10;               // 0=z (blocks 0-31), 1=r (32-63)
    const int c1   = vc & 1023;              // 32 cols
    const int goff = gate ? H_ : 0;
    const int cg0  = blockIdx.x * 16;        // phase-2 cols

    const size_t lw = (size_t)layer * H_ * H_;

    // ---- resident weight fragments ----
    uint32_t w1f[4][8][2];                   // phase 1: 4 n-tiles x 8 k-steps
    uint32_t w2h[2][8][2], w2l[2][8][2];     // phase 2: 2 n-tiles
    {
        const unsigned short* W1 = gate ? g_wrhf : g_wzhf;
#pragma unroll
        for (int nt = 0; nt < 4; nt++)
#pragma unroll
            for (int ks = 0; ks < 8; ks++) {
                int row = c1 + nt * 8 + g;
                int kw = warp * 64 + ks * 8 + tg;
                const uint32_t* wr = (const uint32_t*)(W1 + lw + (size_t)row * H_);
                w1f[nt][ks][0] = wr[kw];
                w1f[nt][ks][1] = wr[kw + 4];
            }
#pragma unroll
        for (int nt = 0; nt < 2; nt++)
#pragma unroll
            for (int ks = 0; ks < 8; ks++) {
                int row = cg0 + nt * 8 + g;
                int kw = warp * 64 + ks * 8 + tg;
                const uint32_t* wr = (const uint32_t*)(g_wghh16 + lw + (size_t)row * H_);
                w2h[nt][ks][0] = wr[kw];
                w2h[nt][ks][1] = wr[kw + 4];
                const uint32_t* wr2 = (const uint32_t*)(g_wghl16 + lw + (size_t)row * H_);
                w2l[nt][ks][0] = wr2[kw];
                w2l[nt][ks][1] = wr2[kw + 4];
            }
    }

    // epilogue index maps
    // phase 1: 4 outputs/thread over 32 b x 32 cols
    int e1b[4], e1c[4];
#pragma unroll
    for (int i = 0; i < 4; i++) {
        int idx = tid + 256 * i;
        e1b[i] = idx >> 5;
        e1c[i] = idx & 31;
    }
    // phase 2: 2 outputs/thread over 32 b x 16 cols
    int e2b[2], e2c[2];
#pragma unroll
    for (int i = 0; i < 2; i++) {
        int idx = tid + 256 * i;
        e2b[i] = idx >> 4;
        e2c[i] = idx & 15;
    }

    // prefetch phase-1 gx for t=0
    float gxp[4];
#pragma unroll
    for (int i = 0; i < 4; i++)
        gxp[i] = __ldcg(&g_gx[((size_t)0 * B_ + e1b[i]) * N3_ + goff + c1 + e1c[i]]);

    for (int t = 0; t < S_; t++) {
        // ================= phase 1: z and r =================
        float hown[4];
        if (gate) {
#pragma unroll
            for (int i = 0; i < 4; i++)
                hown[i] = __ldcg(&g_h[e1b[i] * H_ + c1 + e1c[i]]);
        }
        stage_one(g_hf, s_t0);
        // prefetch phase-2 constants (safe: constant buffer / own-written h)
        float gxg[2], hv[2];
#pragma unroll
        for (int i = 0; i < 2; i++) {
            gxg[i] = __ldcg(&g_gx[((size_t)t * B_ + e2b[i]) * N3_ + 2 * H_ + cg0 + e2c[i]]);
            hv[i]  = g_h[e2b[i] * H_ + cg0 + e2c[i]];   // own cols
        }
        __syncthreads();

        float acc[2][4][4];
#pragma unroll
        for (int mt = 0; mt < 2; mt++)
#pragma unroll
            for (int nt = 0; nt < 4; nt++)
#pragma unroll
                for (int i = 0; i < 4; i++) acc[mt][nt][i] = 0.f;

#pragma unroll
        for (int ks = 0; ks < 8; ks++) {
            const int kw = warp * 64 + ks * 8 + tg;
            uint32_t ah[2][4];
#pragma unroll
            for (int mt = 0; mt < 2; mt++) {
                const uint32_t* b0 = s_t0 + (mt * 16 + g) * SW_PW;
                const uint32_t* b1 = b0 + 8 * SW_PW;
                ah[mt][0] = b0[kw];
                ah[mt][1] = b1[kw];
                ah[mt][2] = b0[kw + 4];
                ah[mt][3] = b1[kw + 4];
            }
#pragma unroll
            for (int mt = 0; mt < 2; mt++)
#pragma unroll
                for (int nt = 0; nt < 4; nt++)
                    mma_f16(acc[mt][nt], ah[mt], w1f[nt][ks]);
        }

        // cross-warp K reduction
#pragma unroll
        for (int mt = 0; mt < 2; mt++)
#pragma unroll
            for (int nt = 0; nt < 4; nt++)
#pragma unroll
                for (int i = 0; i < 4; i++) {
                    int row = mt * 16 + g + (i >> 1) * 8;
                    int col = nt * 8 + tg * 2 + (i & 1);
                    red[(warp * 32 + row) * RED_STRIDE + col] = acc[mt][nt][i];
                }
        __syncthreads();

#pragma unroll
        for (int i = 0; i < 4; i++) {
            float v = 0.f;
#pragma unroll
            for (int w = 0; w < 8; w++)
                v += red[(w * 32 + e1b[i]) * RED_STRIDE + e1c[i]];
            float s = sigmoidf_(v + gxp[i]);
            int j = c1 + e1c[i];
            if (gate == 0) {
                g_z[e1b[i] * H_ + j] = s;
            } else {
                float rh = s * hown[i];
                unsigned short hh, hl;
                split16(rh, hh, hl);
                g_rhh[e1b[i] * H_ + j] = hh;
                g_rhl[e1b[i] * H_ + j] = hl;
            }
        }

        grid_sync();

        // ================= phase 2: g and h update =================
        float zv[2];
#pragma unroll
        for (int i = 0; i < 2; i++)
            zv[i] = __ldcg(&g_z[e2b[i] * H_ + cg0 + e2c[i]]);   // post-barrier
        stage_two(g_rhh, g_rhl, s_t0, s_t1);
        __syncthreads();

        float acc2[2][2][4];
#pragma unroll
        for (int mt = 0; mt < 2; mt++)
#pragma unroll
            for (int nt = 0; nt < 2; nt++)
#pragma unroll
                for (int i = 0; i < 4; i++) acc2[mt][nt][i] = 0.f;

#pragma unroll
        for (int ks = 0; ks < 8; ks++) {
            const int kw = warp * 64 + ks * 8 + tg;
            uint32_t ah[2][4], al[2][4];
#pragma unroll
            for (int mt = 0; mt < 2; mt++) {
                const uint32_t* b0 = s_t0 + (mt * 16 + g) * SW_PW;
                const uint32_t* b1 = b0 + 8 * SW_PW;
                ah[mt][0] = b0[kw];
                ah[mt][1] = b1[kw];
                ah[mt][2] = b0[kw + 4];
                ah[mt][3] = b1[kw + 4];
                const uint32_t* c0 = s_t1 + (mt * 16 + g) * SW_PW;
                const uint32_t* c1p = c0 + 8 * SW_PW;
                al[mt][0] = c0[kw];
                al[mt][1] = c1p[kw];
                al[mt][2] = c0[kw + 4];
                al[mt][3] = c1p[kw + 4];
            }
#pragma unroll
            for (int mt = 0; mt < 2; mt++)
#pragma unroll
                for (int nt = 0; nt < 2; nt++) {
                    mma_f16(acc2[mt][nt], ah[mt], w2h[nt][ks]);
                    mma_f16(acc2[mt][nt], ah[mt], w2l[nt][ks]);
                    mma_f16(acc2[mt][nt], al[mt], w2h[nt][ks]);
                }
        }

#pragma unroll
        for (int mt = 0; mt < 2; mt++)
#pragma unroll
            for (int nt = 0; nt < 2; nt++)
#pragma unroll
                for (int i = 0; i < 4; i++) {
                    int row = mt * 16 + g + (i >> 1) * 8;
                    int col = nt * 8 + tg * 2 + (i & 1);
                    red[(warp * 32 + row) * RED_STRIDE + col] = acc2[mt][nt][i];
                }
        __syncthreads();

#pragma unroll
        for (int i = 0; i < 2; i++) {
            float v = 0.f;
#pragma unroll
            for (int w = 0; w < 8; w++)
                v += red[(w * 32 + e2b[i]) * RED_STRIDE + e2c[i]];
            int j = cg0 + e2c[i];
            size_t row = (size_t)t * B_ + e2b[i];
            float gv = tanhf(v + gxg[i]);
            float hn = fmaf(zv[i], gv - hv[i], hv[i]);

            g_h[e2b[i] * H_ + j] = hn;
            g_hf[e2b[i] * H_ + j] = __half_as_ushort(__float2half(hn));
            unsigned short bh, bl;
            split1(hn, bh, bl);
            g_seqh[row * H_ + j] = bh;
            g_seql[row * H_ + j] = bl;
            if (hid_out && t == S_ - 1)
                hid_out[((size_t)e2b[i] * L_ + layer) * H_ + j] = hn;
        }

        // prefetch next step's phase-1 gx (constant data)
        if (t + 1 < S_) {
#pragma unroll
            for (int i = 0; i < 4; i++)
                gxp[i] = __ldcg(&g_gx[((size_t)(t + 1) * B_ + e1b[i]) * N3_ + goff + c1 + e1c[i]]);
        }

        grid_sync();
    }
}

// ---------------------------------------------------------------------------
// Launch
// ---------------------------------------------------------------------------
extern "C" void kernel_launch(void* const* d_in, const int* in_sizes, int n_in,
                              void* d_out, int out_size) {
    (void)in_sizes; (void)n_in;
    const float* x   = (const float*)d_in[0];
    const float* h0  = (const float*)d_in[1];
    const float* Wzx = (const float*)d_in[2];
    const float* bz  = (const float*)d_in[3];
    const float* Wzh = (const float*)d_in[4];
    const float* Wrx = (const float*)d_in[5];
    const float* br  = (const float*)d_in[6];
    const float* Wrh = (const float*)d_in[7];
    const float* Wgx = (const float*)d_in[8];
    const float* bg  = (const float*)d_in[9];
    const float* Wgh = (const float*)d_in[10];
    const float* Wo  = (const float*)d_in[11];
    const float* bo  = (const float*)d_in[12];

    float* out = (float*)d_out;
    float* y_out = out;
    const long long need = (long long)B_ * S_ * OUT_ + (long long)B_ * L_ * H_;
    float* hid_out = ((long long)out_size >= need) ? out + (size_t)B_ * S_ * OUT_
                                                   : nullptr;

    cudaFuncSetAttribute(k_gru_recur,
        cudaFuncAttributeMaxDynamicSharedMemorySize, SMEMR);

    // operand prep
    k_transpose_x<<<M_, 256>>>(x);
    const int wbig4 = (L_ * H_ * IN_) / 4;   // 524288
    const int wout4 = (OUT_ * H_) / 4;       // 262144
    k_split<<<wbig4 / 256, 256>>>(Wzx, 0, wbig4);
    k_split<<<wbig4 / 256, 256>>>(Wrx, 1, wbig4);
    k_split<<<wbig4 / 256, 256>>>(Wgx, 2, wbig4);
    k_split<<<wout4 / 256, 256>>>(Wo, 3, wout4);
    k_split16<<<wbig4 / 256, 256>>>(Wzh, 0, wbig4);
    k_split16<<<wbig4 / 256, 256>>>(Wrh, 1, wbig4);
    k_split16<<<wbig4 / 256, 256>>>(Wgh, 2, wbig4);

    dim3 tgrid(1024 / 64, M_ / 128);   // (16, 128)

    for (int layer = 0; layer < L_; layer++) {
        k_prep<<<(B_ * H_) / 256, 256>>>(h0, layer);

        const int woff = layer * H_ * IN_;
        k_hmma<<<tgrid, 256>>>(layer, 0, woff, bz + (size_t)layer * H_,
                               nullptr, N3_, 0, 0);
        k_hmma<<<tgrid, 256>>>(layer, 1, woff, br + (size_t)layer * H_,
                               nullptr, N3_, H_, 0);
        k_hmma<<<tgrid, 256>>>(layer, 2, woff, bg + (size_t)layer * H_,
                               nullptr, N3_, 2 * H_, 0);

        k_gru_recur<<<NBLK, 256, SMEMR>>>(layer, hid_out);
    }

    // output projection
    k_hmma<<<tgrid, 256>>>(1, 3, 0, bo, y_out, OUT_, 0, 1);
}

// round 11
// speedup vs baseline: 1.2175x; 1.2175x over previous
#include <cuda_runtime.h>
#include <cuda_bf16.h>
#include <cuda_fp16.h>
#include <math.h>
#include <stdint.h>

// ---------------------------------------------------------------------------
// MultilayerGRU: B=32, S=512, I=H=O=1024, L=2
// R11: revert to R9 structure (NBLK=128, proven 12.03ms). One change:
//      phase 2 now single-fp16 rh + single-fp16 Wgh (1 MMA term), mirroring
//      phase 1 — halves stage-2 broadcast bytes, cuts phase-2 MMAs 3x.
//      fp32 master h kept. Big GEMMs = proven bf16 hi/lo k_hmma.
// ---------------------------------------------------------------------------

#define B_  32
#define S_  512
#define IN_ 1024
#define H_  1024
#define OUT_ 1024
#define L_  2
#define M_  (B_ * S_)      /* 16384 */
#define N3_ (3 * H_)       /* 3072  */
#define NBLK 128

// ---------------- device scratch ------------------------------------------
__device__ float g_gx[(size_t)M_ * N3_];   // x-projections for current layer
__device__ float g_h[B_ * H_];             // fp32 master hidden state
__device__ float g_z[B_ * H_];             // z gate

__device__ __align__(16) unsigned short g_hf[B_ * H_];    // h fp16
__device__ __align__(16) unsigned short g_rhf[B_ * H_];   // r*h fp16

// bf16 hi/lo operand buffers (GEMM path)
__device__ __align__(16) unsigned short g_xh[(size_t)M_ * IN_],  g_xl[(size_t)M_ * IN_];
__device__ __align__(16) unsigned short g_seqh[(size_t)M_ * H_], g_seql[(size_t)M_ * H_];
__device__ __align__(16) unsigned short g_wzxh[(size_t)L_ * H_ * IN_], g_wzxl[(size_t)L_ * H_ * IN_];
__device__ __align__(16) unsigned short g_wrxh[(size_t)L_ * H_ * IN_], g_wrxl[(size_t)L_ * H_ * IN_];
__device__ __align__(16) unsigned short g_wgxh[(size_t)L_ * H_ * IN_], g_wgxl[(size_t)L_ * H_ * IN_];
__device__ __align__(16) unsigned short g_woh[(size_t)OUT_ * H_],      g_wol[(size_t)OUT_ * H_];

// fp16 recurrence weights (all single-precision fp16 now)
__device__ __align__(16) unsigned short g_wzhf[(size_t)L_ * H_ * H_];
__device__ __align__(16) unsigned short g_wrhf[(size_t)L_ * H_ * H_];
__device__ __align__(16) unsigned short g_wghf[(size_t)L_ * H_ * H_];

// grid barrier (generation-based; replay-safe)
__device__ unsigned g_bar_count = 0;
__device__ volatile unsigned g_bar_gen = 0;

__device__ __forceinline__ void grid_sync() {
    __syncthreads();
    if (threadIdx.x == 0) {
        __threadfence();
        unsigned gen = g_bar_gen;
        if (atomicAdd(&g_bar_count, 1u) == NBLK - 1u) {
            g_bar_count = 0;
            __threadfence();
            g_bar_gen = gen + 1u;
        } else {
            while (g_bar_gen == gen) { }
        }
    }
    __syncthreads();
}

// ---------------------------------------------------------------------------
__device__ __forceinline__ void split1(float v, unsigned short& h, unsigned short& l) {
    __nv_bfloat16 hb = __float2bfloat16(v);
    float r = v - __bfloat162float(hb);
    __nv_bfloat16 lb = __float2bfloat16(r);
    h = __bfloat16_as_ushort(hb);
    l = __bfloat16_as_ushort(lb);
}

// mma.sync m16n8k16 row.col, bf16 and fp16 flavors
__device__ __forceinline__ void mma_bf16(float* c, const uint32_t* a, const uint32_t* b) {
    asm volatile(
        "mma.sync.aligned.m16n8k16.row.col.f32.bf16.bf16.f32 "
        "{%0,%1,%2,%3}, {%4,%5,%6,%7}, {%8,%9}, {%0,%1,%2,%3};"
        : "+f"(c[0]), "+f"(c[1]), "+f"(c[2]), "+f"(c[3])
        : "r"(a[0]), "r"(a[1]), "r"(a[2]), "r"(a[3]), "r"(b[0]), "r"(b[1]));
}

__device__ __forceinline__ void mma_f16(float* c, const uint32_t* a, const uint32_t* b) {
    asm volatile(
        "mma.sync.aligned.m16n8k16.row.col.f32.f16.f16.f32 "
        "{%0,%1,%2,%3}, {%4,%5,%6,%7}, {%8,%9}, {%0,%1,%2,%3};"
        : "+f"(c[0]), "+f"(c[1]), "+f"(c[2]), "+f"(c[3])
        : "r"(a[0]), "r"(a[1]), "r"(a[2]), "r"(a[3]), "r"(b[0]), "r"(b[1]));
}

__device__ __forceinline__ float sigmoidf_(float x) {
    return 1.f / (1.f + expf(-x));
}

// ---------------------------------------------------------------------------
// x[b][t][i] -> hi/lo bf16 [t*B+b][i]
// ---------------------------------------------------------------------------
__global__ void k_transpose_x(const float* __restrict__ x) {
    int row = blockIdx.x;
    int t = row / B_;
    int b = row % B_;
    const float4* src = (const float4*)(x + ((size_t)b * S_ + t) * IN_);
    ushort4* dh = (ushort4*)(g_xh + (size_t)row * IN_);
    ushort4* dl = (ushort4*)(g_xl + (size_t)row * IN_);
    for (int i = threadIdx.x; i < IN_ / 4; i += blockDim.x) {
        float4 v = src[i];
        ushort4 h, l;
        split1(v.x, h.x, l.x);
        split1(v.y, h.y, l.y);
        split1(v.z, h.z, l.z);
        split1(v.w, h.w, l.w);
        dh[i] = h;
        dl[i] = l;
    }
}

// ---------------------------------------------------------------------------
// weight splits
// ---------------------------------------------------------------------------
__global__ void k_split(const float* __restrict__ src, int wsel, int n4) {
    int i = blockIdx.x * blockDim.x + threadIdx.x;
    if (i >= n4) return;
    unsigned short* hi;
    unsigned short* lo;
    switch (wsel) {
        case 0: hi = g_wzxh; lo = g_wzxl; break;
        case 1: hi = g_wrxh; lo = g_wrxl; break;
        case 2: hi = g_wgxh; lo = g_wgxl; break;
        default: hi = g_woh;  lo = g_wol; break;
    }
    float4 v = ((const float4*)src)[i];
    ushort4 h, l;
    split1(v.x, h.x, l.x);
    split1(v.y, h.y, l.y);
    split1(v.z, h.z, l.z);
    split1(v.w, h.w, l.w);
    ((ushort4*)hi)[i] = h;
    ((ushort4*)lo)[i] = l;
}

__global__ void k_split16(const float* __restrict__ src, int wsel, int n4) {
    int i = blockIdx.x * blockDim.x + threadIdx.x;
    if (i >= n4) return;
    float4 v = ((const float4*)src)[i];
    unsigned short* hi = (wsel == 0) ? g_wzhf : (wsel == 1) ? g_wrhf : g_wghf;
    ushort4 h;
    h.x = __half_as_ushort(__float2half(v.x));
    h.y = __half_as_ushort(__float2half(v.y));
    h.z = __half_as_ushort(__float2half(v.z));
    h.w = __half_as_ushort(__float2half(v.w));
    ((ushort4*)hi)[i] = h;
}

// ---------------------------------------------------------------------------
// k_prep: g_h / g_hf from h0[b][layer][:]; reset barrier.
// ---------------------------------------------------------------------------
__global__ void k_prep(const float* __restrict__ h0, int layer) {
    int idx = blockIdx.x * blockDim.x + threadIdx.x;  // [0, B*H)
    if (idx == 0) { g_bar_count = 0; g_bar_gen = 0; }
    int b = idx / H_;
    int c = idx % H_;
    float v = h0[((size_t)b * L_ + layer) * H_ + c];
    g_h[idx] = v;
    g_hf[idx] = __half_as_ushort(__float2half(v));
}

// ---------------------------------------------------------------------------
// HMMA split-bf16 GEMM (unchanged, proven).
// ---------------------------------------------------------------------------
#define HMP 40

__global__ void __launch_bounds__(256) k_hmma(
    int asel, int wsel, int woff,
    const float* __restrict__ bias, float* __restrict__ Cout,
    int ldc, int col0, int permC)
{
    __shared__ __align__(16) unsigned short As_h[128 * HMP];
    __shared__ __align__(16) unsigned short As_l[128 * HMP];
    __shared__ __align__(16) unsigned short Bs_h[64 * HMP];
    __shared__ __align__(16) unsigned short Bs_l[64 * HMP];

    const int tid = threadIdx.x;
    const int m0 = blockIdx.y * 128, n0 = blockIdx.x * 64;

    const unsigned short* Ah = asel ? g_seqh : g_xh;
    const unsigned short* Al = asel ? g_seql : g_xl;
    const unsigned short* Wh;
    const unsigned short* Wl;
    switch (wsel) {
        case 0: Wh = g_wzxh; Wl = g_wzxl; break;
        case 1: Wh = g_wrxh; Wl = g_wrxl; break;
        case 2: Wh = g_wgxh; Wl = g_wgxl; break;
        default: Wh = g_woh; Wl = g_wol; break;
    }
    Wh += woff; Wl += woff;

    const int ar0 = (2 * tid) >> 2,     au0 = (2 * tid) & 3;
    const int ar1 = (2 * tid + 1) >> 2, au1 = (2 * tid + 1) & 3;
    const int br  = tid >> 2,           bu  = tid & 3;

    const int warp = tid >> 5, lane = tid & 31;
    const int g = lane >> 2, tg = lane & 3;
    const int wm = warp >> 1, wn = warp & 1;

    float acc[2][4][4];
#pragma unroll
    for (int mt = 0; mt < 2; mt++)
#pragma unroll
        for (int nt = 0; nt < 4; nt++)
#pragma unroll
            for (int i = 0; i < 4; i++) acc[mt][nt][i] = 0.f;

    const uint32_t* Awh = (const uint32_t*)As_h;
    const uint32_t* Awl = (const uint32_t*)As_l;
    const uint32_t* Bwh = (const uint32_t*)Bs_h;
    const uint32_t* Bwl = (const uint32_t*)Bs_l;

    uint4 vah0, vah1, val0, val1, vbh, vbl;
    vah0 = *(const uint4*)(Ah + (size_t)(m0 + ar0) * 1024 + au0 * 8);
    vah1 = *(const uint4*)(Ah + (size_t)(m0 + ar1) * 1024 + au1 * 8);
    val0 = *(const uint4*)(Al + (size_t)(m0 + ar0) * 1024 + au0 * 8);
    val1 = *(const uint4*)(Al + (size_t)(m0 + ar1) * 1024 + au1 * 8);
    vbh  = *(const uint4*)(Wh + (size_t)(n0 + br) * 1024 + bu * 8);
    vbl  = *(const uint4*)(Wl + (size_t)(n0 + br) * 1024 + bu * 8);

    for (int kc = 0; kc < 32; kc++) {
        __syncthreads();
        *(uint4*)(As_h + ar0 * HMP + au0 * 8) = vah0;
        *(uint4*)(As_h + ar1 * HMP + au1 * 8) = vah1;
        *(uint4*)(As_l + ar0 * HMP + au0 * 8) = val0;
        *(uint4*)(As_l + ar1 * HMP + au1 * 8) = val1;
        *(uint4*)(Bs_h + br * HMP + bu * 8) = vbh;
        *(uint4*)(Bs_l + br * HMP + bu * 8) = vbl;
        if (kc + 1 < 32) {
            int ko = (kc + 1) * 32;
            vah0 = *(const uint4*)(Ah + (size_t)(m0 + ar0) * 1024 + ko + au0 * 8);
            vah1 = *(const uint4*)(Ah + (size_t)(m0 + ar1) * 1024 + ko + au1 * 8);
            val0 = *(const uint4*)(Al + (size_t)(m0 + ar0) * 1024 + ko + au0 * 8);
            val1 = *(const uint4*)(Al + (size_t)(m0 + ar1) * 1024 + ko + au1 * 8);
            vbh  = *(const uint4*)(Wh + (size_t)(n0 + br) * 1024 + ko + bu * 8);
            vbl  = *(const uint4*)(Wl + (size_t)(n0 + br) * 1024 + ko + bu * 8);
        }
        __syncthreads();

#pragma unroll
        for (int ks = 0; ks < 2; ks++) {
            const int kw = ks * 8 + tg;
            uint32_t ahf[2][4], alf[2][4];
#pragma unroll
            for (int mt = 0; mt < 2; mt++) {
                int rb = (wm * 32 + mt * 16 + g) * 20 + kw;
                ahf[mt][0] = Awh[rb];
                ahf[mt][1] = Awh[rb + 160];
                ahf[mt][2] = Awh[rb + 4];
                ahf[mt][3] = Awh[rb + 164];
                alf[mt][0] = Awl[rb];
                alf[mt][1] = Awl[rb + 160];
                alf[mt][2] = Awl[rb + 4];
                alf[mt][3] = Awl[rb + 164];
            }
            uint32_t bhf[4][2], blf[4][2];
#pragma unroll
            for (int nt = 0; nt < 4; nt++) {
                int rb = (wn * 32 + nt * 8 + g) * 20 + kw;
                bhf[nt][0] = Bwh[rb];
                bhf[nt][1] = Bwh[rb + 4];
                blf[nt][0] = Bwl[rb];
                blf[nt][1] = Bwl[rb + 4];
            }
#pragma unroll
            for (int mt = 0; mt < 2; mt++)
#pragma unroll
                for (int nt = 0; nt < 4; nt++) {
                    mma_bf16(acc[mt][nt], ahf[mt], bhf[nt]);
                    mma_bf16(acc[mt][nt], ahf[mt], blf[nt]);
                    mma_bf16(acc[mt][nt], alf[mt], bhf[nt]);
                }
        }
    }

#pragma unroll
    for (int mt = 0; mt < 2; mt++) {
#pragma unroll
        for (int nt = 0; nt < 4; nt++) {
            int mrow = m0 + wm * 32 + mt * 16 + g;
            int ncol = n0 + wn * 32 + nt * 8 + tg * 2;
            float bx = bias[ncol], by = bias[ncol + 1];
#pragma unroll
            for (int half = 0; half < 2; half++) {
                int m = mrow + half * 8;
                float2 o;
                o.x = acc[mt][nt][half * 2 + 0] + bx;
                o.y = acc[mt][nt][half * 2 + 1] + by;
                float* dst;
                if (permC) {
                    int b = m & (B_ - 1);
                    int t = m >> 5;
                    dst = Cout + ((size_t)b * S_ + t) * ldc + ncol;
                } else {
                    dst = g_gx + (size_t)m * ldc + col0 + ncol;
                }
                *(float2*)dst = o;
            }
        }
    }
}

// ---------------------------------------------------------------------------
// fp16 tensor-core recurrence (R9 structure, NBLK=128).
//   Phase 1: 16 (z|r) cols/block, fp16 h x fp16 W, 1 MMA term.
//   Phase 2: 8 g cols/block, fp16 rh x fp16 Wgh, 1 MMA term.
// ---------------------------------------------------------------------------
#define SW_PW 516
#define TILE_B (32 * SW_PW * 4)            /* 66048 bytes tile buffer */
#define RED_STRIDE 18
#define RED_B (8 * 32 * RED_STRIDE * 4)    /* 18432 */
#define SMEMR (TILE_B + RED_B)             /* 84480 */

// stage 32x1024 fp16 (512 words/row) from gmem into the smem tile
__device__ __forceinline__ void stage_one(
    const unsigned short* __restrict__ gsrc, uint32_t* __restrict__ s)
{
    const int tid = threadIdx.x;
#pragma unroll
    for (int rr = 0; rr < 2; rr++) {
        uint4 v[8];
#pragma unroll
        for (int it = 0; it < 8; it++) {
            int idx = tid + 256 * (rr * 8 + it);
            int row = idx >> 7;
            int u = idx & 127;
            v[it] = __ldcg((const uint4*)(gsrc + (size_t)row * H_) + u);
        }
#pragma unroll
        for (int it = 0; it < 8; it++) {
            int idx = tid + 256 * (rr * 8 + it);
            int row = idx >> 7;
            int u = idx & 127;
            *(uint4*)(s + row * SW_PW + u * 4) = v[it];
        }
    }
}

__global__ void __launch_bounds__(256, 1) k_gru_recur(
    int layer, float* __restrict__ hid_out)
{
    extern __shared__ char smem[];
    uint32_t* s_t0 = (uint32_t*)smem;                    // tile
    float*    red  = (float*)(smem + TILE_B);            // [8][32][18]

    const int tid = threadIdx.x;
    const int warp = tid >> 5, lane = tid & 31;
    const int g = lane >> 2, tg = lane & 3;

    // ---- ownership ----
    const int vc   = blockIdx.x * 16;        // [0,2048)
    const int gate = vc >> 10;               // 0=z, 1=r
    const int c1   = vc & 1023;
    const int goff = gate ? H_ : 0;
    const int cg0  = blockIdx.x * 8;         // phase-2 cols

    const size_t lw = (size_t)layer * H_ * H_;

    // ---- resident weight fragments (single fp16) ----
    uint32_t w1f[2][8][2];                   // phase 1: 2 n-tiles x 8 k-steps
    uint32_t w2f[8][2];                      // phase 2: 1 n-tile
    {
        const unsigned short* W1 = gate ? g_wrhf : g_wzhf;
#pragma unroll
        for (int nt = 0; nt < 2; nt++)
#pragma unroll
            for (int ks = 0; ks < 8; ks++) {
                int row = c1 + nt * 8 + g;
                int kw = warp * 64 + ks * 8 + tg;
                const uint32_t* wr = (const uint32_t*)(W1 + lw + (size_t)row * H_);
                w1f[nt][ks][0] = wr[kw];
                w1f[nt][ks][1] = wr[kw + 4];
            }
#pragma unroll
        for (int ks = 0; ks < 8; ks++) {
            int row = cg0 + g;
            int kw = warp * 64 + ks * 8 + tg;
            const uint32_t* wr = (const uint32_t*)(g_wghf + lw + (size_t)row * H_);
            w2f[ks][0] = wr[kw];
            w2f[ks][1] = wr[kw + 4];
        }
    }

    // epilogue index maps
    const int e1b0 = tid >> 4,          e1c0 = tid & 15;
    const int e1b1 = (tid + 256) >> 4,  e1c1 = (tid + 256) & 15;
    const int e2b = tid >> 3, e2c = tid & 7;
    const int j2 = cg0 + e2c;

    // prefetch phase-1 gx for t=0
    float gxp0 = __ldcg(&g_gx[(size_t)e1b0 * N3_ + goff + c1 + e1c0]);
    float gxp1 = __ldcg(&g_gx[(size_t)e1b1 * N3_ + goff + c1 + e1c1]);

    for (int t = 0; t < S_; t++) {
        // ================= phase 1: z and r =================
        float hown0 = 0.f, hown1 = 0.f;
        if (gate) {
            hown0 = __ldcg(&g_h[e1b0 * H_ + c1 + e1c0]);
            hown1 = __ldcg(&g_h[e1b1 * H_ + c1 + e1c1]);
        }
        stage_one(g_hf, s_t0);
        // prefetch phase-2 constants (constant buffer / own-written h)
        float gxg = __ldcg(&g_gx[((size_t)t * B_ + e2b) * N3_ + 2 * H_ + j2]);
        float hv = g_h[e2b * H_ + j2];
        __syncthreads();

        float acc[2][2][4];
#pragma unroll
        for (int mt = 0; mt < 2; mt++)
#pragma unroll
            for (int nt = 0; nt < 2; nt++)
#pragma unroll
                for (int i = 0; i < 4; i++) acc[mt][nt][i] = 0.f;

#pragma unroll
        for (int ks = 0; ks < 8; ks++) {
            const int kw = warp * 64 + ks * 8 + tg;
            uint32_t ah[2][4];
#pragma unroll
            for (int mt = 0; mt < 2; mt++) {
                const uint32_t* b0 = s_t0 + (mt * 16 + g) * SW_PW;
                const uint32_t* b1 = b0 + 8 * SW_PW;
                ah[mt][0] = b0[kw];
                ah[mt][1] = b1[kw];
                ah[mt][2] = b0[kw + 4];
                ah[mt][3] = b1[kw + 4];
            }
#pragma unroll
            for (int mt = 0; mt < 2; mt++)
#pragma unroll
                for (int nt = 0; nt < 2; nt++)
                    mma_f16(acc[mt][nt], ah[mt], w1f[nt][ks]);
        }

        // cross-warp K reduction
#pragma unroll
        for (int mt = 0; mt < 2; mt++)
#pragma unroll
            for (int nt = 0; nt < 2; nt++)
#pragma unroll
                for (int i = 0; i < 4; i++) {
                    int row = mt * 16 + g + (i >> 1) * 8;
                    int col = nt * 8 + tg * 2 + (i & 1);
                    red[(warp * 32 + row) * RED_STRIDE + col] = acc[mt][nt][i];
                }
        __syncthreads();

        {
            float v0 = 0.f, v1 = 0.f;
#pragma unroll
            for (int w = 0; w < 8; w++) {
                v0 += red[(w * 32 + e1b0) * RED_STRIDE + e1c0];
                v1 += red[(w * 32 + e1b1) * RED_STRIDE + e1c1];
            }
            float s0 = sigmoidf_(v0 + gxp0);
            float s1 = sigmoidf_(v1 + gxp1);
            if (gate == 0) {
                g_z[e1b0 * H_ + c1 + e1c0] = s0;
                g_z[e1b1 * H_ + c1 + e1c1] = s1;
            } else {
                g_rhf[e1b0 * H_ + c1 + e1c0] =
                    __half_as_ushort(__float2half(s0 * hown0));
                g_rhf[e1b1 * H_ + c1 + e1c1] =
                    __half_as_ushort(__float2half(s1 * hown1));
            }
        }

        grid_sync();

        // ================= phase 2: g and h update =================
        float zv = __ldcg(&g_z[e2b * H_ + j2]);   // safe post-barrier
        stage_one(g_rhf, s_t0);
        __syncthreads();

        float acc2[2][4];
#pragma unroll
        for (int mt = 0; mt < 2; mt++)
#pragma unroll
            for (int i = 0; i < 4; i++) acc2[mt][i] = 0.f;

#pragma unroll
        for (int ks = 0; ks < 8; ks++) {
            const int kw = warp * 64 + ks * 8 + tg;
            uint32_t ah[2][4];
#pragma unroll
            for (int mt = 0; mt < 2; mt++) {
                const uint32_t* b0 = s_t0 + (mt * 16 + g) * SW_PW;
                const uint32_t* b1 = b0 + 8 * SW_PW;
                ah[mt][0] = b0[kw];
                ah[mt][1] = b1[kw];
                ah[mt][2] = b0[kw + 4];
                ah[mt][3] = b1[kw + 4];
            }
#pragma unroll
            for (int mt = 0; mt < 2; mt++)
                mma_f16(acc2[mt], ah[mt], w2f[ks]);
        }

#pragma unroll
        for (int mt = 0; mt < 2; mt++)
#pragma unroll
            for (int i = 0; i < 4; i++) {
                int row = mt * 16 + g + (i >> 1) * 8;
                int col = tg * 2 + (i & 1);
                red[(warp * 32 + row) * RED_STRIDE + col] = acc2[mt][i];
            }
        __syncthreads();

        {
            float v = 0.f;
#pragma unroll
            for (int w = 0; w < 8; w++) v += red[(w * 32 + e2b) * RED_STRIDE + e2c];
            size_t row = (size_t)t * B_ + e2b;
            float gv = tanhf(v + gxg);
            float hn = fmaf(zv, gv - hv, hv);

            g_h[e2b * H_ + j2] = hn;
            g_hf[e2b * H_ + j2] = __half_as_ushort(__float2half(hn));
            unsigned short bh, bl;
            split1(hn, bh, bl);
            g_seqh[row * H_ + j2] = bh;
            g_seql[row * H_ + j2] = bl;
            if (hid_out && t == S_ - 1)
                hid_out[((size_t)e2b * L_ + layer) * H_ + j2] = hn;
        }

        // prefetch next step's phase-1 gx (constant data)
        if (t + 1 < S_) {
            gxp0 = __ldcg(&g_gx[((size_t)(t + 1) * B_ + e1b0) * N3_ + goff + c1 + e1c0]);
            gxp1 = __ldcg(&g_gx[((size_t)(t + 1) * B_ + e1b1) * N3_ + goff + c1 + e1c1]);
        }

        grid_sync();
    }
}

// ---------------------------------------------------------------------------
// Launch
// ---------------------------------------------------------------------------
extern "C" void kernel_launch(void* const* d_in, const int* in_sizes, int n_in,
                              void* d_out, int out_size) {
    (void)in_sizes; (void)n_in;
    const float* x   = (const float*)d_in[0];
    const float* h0  = (const float*)d_in[1];
    const float* Wzx = (const float*)d_in[2];
    const float* bz  = (const float*)d_in[3];
    const float* Wzh = (const float*)d_in[4];
    const float* Wrx = (const float*)d_in[5];
    const float* br  = (const float*)d_in[6];
    const float* Wrh = (const float*)d_in[7];
    const float* Wgx = (const float*)d_in[8];
    const float* bg  = (const float*)d_in[9];
    const float* Wgh = (const float*)d_in[10];
    const float* Wo  = (const float*)d_in[11];
    const float* bo  = (const float*)d_in[12];

    float* out = (float*)d_out;
    float* y_out = out;
    const long long need = (long long)B_ * S_ * OUT_ + (long long)B_ * L_ * H_;
    float* hid_out = ((long long)out_size >= need) ? out + (size_t)B_ * S_ * OUT_
                                                   : nullptr;

    cudaFuncSetAttribute(k_gru_recur,
        cudaFuncAttributeMaxDynamicSharedMemorySize, SMEMR);

    // operand prep
    k_transpose_x<<<M_, 256>>>(x);
    const int wbig4 = (L_ * H_ * IN_) / 4;   // 524288
    const int wout4 = (OUT_ * H_) / 4;       // 262144
    k_split<<<wbig4 / 256, 256>>>(Wzx, 0, wbig4);
    k_split<<<wbig4 / 256, 256>>>(Wrx, 1, wbig4);
    k_split<<<wbig4 / 256, 256>>>(Wgx, 2, wbig4);
    k_split<<<wout4 / 256, 256>>>(Wo, 3, wout4);
    k_split16<<<wbig4 / 256, 256>>>(Wzh, 0, wbig4);
    k_split16<<<wbig4 / 256, 256>>>(Wrh, 1, wbig4);
    k_split16<<<wbig4 / 256, 256>>>(Wgh, 2, wbig4);

    dim3 tgrid(1024 / 64, M_ / 128);   // (16, 128)

    for (int layer = 0; layer < L_; layer++) {
        k_prep<<<(B_ * H_) / 256, 256>>>(h0, layer);

        const int woff = layer * H_ * IN_;
        k_hmma<<<tgrid, 256>>>(layer, 0, woff, bz + (size_t)layer * H_,
                               nullptr, N3_, 0, 0);
        k_hmma<<<tgrid, 256>>>(layer, 1, woff, br + (size_t)layer * H_,
                               nullptr, N3_, H_, 0);
        k_hmma<<<tgrid, 256>>>(layer, 2, woff, bg + (size_t)layer * H_,
                               nullptr, N3_, 2 * H_, 0);

        k_gru_recur<<<NBLK, 256, SMEMR>>>(layer, hid_out);
    }

    // output projection
    k_hmma<<<tgrid, 256>>>(1, 3, 0, bo, y_out, OUT_, 0, 1);
}